// round 1
// baseline (speedup 1.0000x reference)
#include <cuda_runtime.h>
#include <cuda_bf16.h>
#include <math.h>

// Problem shape (fixed for this benchmark problem)
#define NTOK 8192      // B*T = 4*2048
#define DIM  512       // D
#define FDIM 1024      // F
#define NEXP 8         // E
#define TOPK 2

// ---------------- scratch (device globals: allocation-free) ----------------
__device__ int   g_expert_count[NEXP];
__device__ int   g_expert_pair[NEXP * NTOK];        // pair id = token*2 + slot
__device__ float g_pair_w[NTOK * TOPK];             // renormalized weight per pair
__device__ float g_hbuf[(size_t)NTOK * TOPK * FDIM]; // SwiGLU activations, 67 MB

// ---------------- kernel 0: zero counts ----------------
__global__ void zero_counts_kernel() {
    if (threadIdx.x < NEXP) g_expert_count[threadIdx.x] = 0;
}

// ---------------- kernel 1: router + dispatch ----------------
// 256 threads = 8 warps, 1 token per warp. router_w cached in smem (16 KB).
__global__ void router_kernel(const float* __restrict__ x,
                              const float* __restrict__ rw,
                              const float* __restrict__ rb) {
    __shared__ float sw[NEXP * DIM];
    int tid = threadIdx.x;
    for (int i = tid; i < NEXP * DIM; i += 256) sw[i] = rw[i];
    __syncthreads();

    int warp = tid >> 5, lane = tid & 31;
    int token = blockIdx.x * 8 + warp;
    if (token >= NTOK) return;

    const float* xr = x + (size_t)token * DIM;
    float acc[NEXP];
#pragma unroll
    for (int e = 0; e < NEXP; e++) acc[e] = 0.f;

    for (int i = lane; i < DIM; i += 32) {
        float xv = xr[i];
#pragma unroll
        for (int e = 0; e < NEXP; e++) acc[e] += xv * sw[e * DIM + i];
    }
#pragma unroll
    for (int e = 0; e < NEXP; e++) {
#pragma unroll
        for (int o = 16; o > 0; o >>= 1)
            acc[e] += __shfl_xor_sync(0xffffffffu, acc[e], o);
    }

    if (lane == 0) {
        float l[NEXP];
#pragma unroll
        for (int e = 0; e < NEXP; e++) l[e] = acc[e] + rb[e];
        // top-1 (first occurrence on ties, matching jax.lax.top_k)
        int e1 = 0; float b1 = l[0];
#pragma unroll
        for (int e = 1; e < NEXP; e++) if (l[e] > b1) { b1 = l[e]; e1 = e; }
        // top-2
        int e2 = -1; float b2 = -INFINITY;
#pragma unroll
        for (int e = 0; e < NEXP; e++)
            if (e != e1 && l[e] > b2) { b2 = l[e]; e2 = e; }
        // renormalized softmax over the two selected logits (numerically stable)
        float t  = expf(b2 - b1);
        float w1 = 1.f / (1.f + t);
        float w2 = t   / (1.f + t);

        int pos1 = atomicAdd(&g_expert_count[e1], 1);
        g_expert_pair[e1 * NTOK + pos1] = token * 2;
        g_pair_w[token * 2] = w1;

        int pos2 = atomicAdd(&g_expert_count[e2], 1);
        g_expert_pair[e2 * NTOK + pos2] = token * 2 + 1;
        g_pair_w[token * 2 + 1] = w2;
    }
}

// ---------------- tiled-GEMM config ----------------
#define BM 64
#define BN 64
#define BK 16
// 256 threads, each computes a 4x4 output tile (x2 matrices in gate_up kernel)

// ---------------- kernel 2: gate_up GEMM + SwiGLU ----------------
// grid = (F/BN=16, NTOK/BM=128, NEXP); blocks past expert count exit early.
__global__ void __launch_bounds__(256)
gateup_kernel(const float* __restrict__ x, const float* __restrict__ wgu) {
    int e = blockIdx.z;
    int count = g_expert_count[e];
    int m0 = blockIdx.y * BM;
    if (m0 >= count) return;
    int n0 = blockIdx.x * BN;

    __shared__ float As[BK][BM];
    __shared__ float Bg[BK][BN];
    __shared__ float Bu[BK][BN];
    __shared__ int   s_pr[BM];

    int tid = threadIdx.x;
    if (tid < BM) {
        int m = m0 + tid;
        s_pr[tid] = (m < count) ? g_expert_pair[e * NTOK + m] : -1;
    }
    __syncthreads();

    const float* wge = wgu + (size_t)e * DIM * (2 * FDIM);

    // A-load mapping: 4 threads per row, each loads float4 of k
    int arow = tid >> 2, ak4 = (tid & 3) * 4;
    int pr_a = s_pr[arow];
    const float* xrow = (pr_a >= 0) ? (x + (size_t)(pr_a >> 1) * DIM) : (const float*)0;

    // B-load mapping: 16 threads per k-row, each loads float4 of n
    int bk = tid >> 4, bn4 = (tid & 15) * 4;

    int tx = tid & 15, ty = tid >> 4;
    float accg[4][4] = {{0.f}}, accu[4][4] = {{0.f}};

    for (int k0 = 0; k0 < DIM; k0 += BK) {
        float4 av = make_float4(0.f, 0.f, 0.f, 0.f);
        if (xrow) av = *reinterpret_cast<const float4*>(xrow + k0 + ak4);
        As[ak4 + 0][arow] = av.x;
        As[ak4 + 1][arow] = av.y;
        As[ak4 + 2][arow] = av.z;
        As[ak4 + 3][arow] = av.w;

        const float* brow = wge + (size_t)(k0 + bk) * (2 * FDIM);
        *reinterpret_cast<float4*>(&Bg[bk][bn4]) =
            *reinterpret_cast<const float4*>(brow + n0 + bn4);
        *reinterpret_cast<float4*>(&Bu[bk][bn4]) =
            *reinterpret_cast<const float4*>(brow + FDIM + n0 + bn4);
        __syncthreads();

#pragma unroll
        for (int k = 0; k < BK; k++) {
            float a[4], bg[4], bu[4];
            *reinterpret_cast<float4*>(a)  = *reinterpret_cast<const float4*>(&As[k][ty * 4]);
            *reinterpret_cast<float4*>(bg) = *reinterpret_cast<const float4*>(&Bg[k][tx * 4]);
            *reinterpret_cast<float4*>(bu) = *reinterpret_cast<const float4*>(&Bu[k][tx * 4]);
#pragma unroll
            for (int i = 0; i < 4; i++)
#pragma unroll
                for (int j = 0; j < 4; j++) {
                    accg[i][j] += a[i] * bg[j];
                    accu[i][j] += a[i] * bu[j];
                }
        }
        __syncthreads();
    }

#pragma unroll
    for (int i = 0; i < 4; i++) {
        int m = ty * 4 + i;
        int pr = s_pr[m];
        if (pr < 0) continue;
        float4 hv;
        float* hp = g_hbuf + (size_t)pr * FDIM + n0 + tx * 4;
        float g0 = accg[i][0], g1 = accg[i][1], g2 = accg[i][2], g3 = accg[i][3];
        hv.x = (g0 / (1.f + expf(-g0))) * accu[i][0];
        hv.y = (g1 / (1.f + expf(-g1))) * accu[i][1];
        hv.z = (g2 / (1.f + expf(-g2))) * accu[i][2];
        hv.w = (g3 / (1.f + expf(-g3))) * accu[i][3];
        *reinterpret_cast<float4*>(hp) = hv;
    }
}

// ---------------- kernel 3: down GEMM + weighted combine ----------------
// grid = (D/BN=8, NTOK/BM=128, NEXP)
__global__ void __launch_bounds__(256)
down_kernel(const float* __restrict__ wd, float* __restrict__ out) {
    int e = blockIdx.z;
    int count = g_expert_count[e];
    int m0 = blockIdx.y * BM;
    if (m0 >= count) return;
    int n0 = blockIdx.x * BN;

    __shared__ float As[BK][BM];
    __shared__ float Bs[BK][BN];
    __shared__ int   s_pr[BM];
    __shared__ float s_w[BM];

    int tid = threadIdx.x;
    if (tid < BM) {
        int m = m0 + tid;
        int pr = (m < count) ? g_expert_pair[e * NTOK + m] : -1;
        s_pr[tid] = pr;
        s_w[tid]  = (pr >= 0) ? g_pair_w[pr] : 0.f;
    }
    __syncthreads();

    const float* wde = wd + (size_t)e * FDIM * DIM;

    int arow = tid >> 2, ak4 = (tid & 3) * 4;
    int pr_a = s_pr[arow];
    const float* hrow = (pr_a >= 0) ? (g_hbuf + (size_t)pr_a * FDIM) : (const float*)0;

    int bk = tid >> 4, bn4 = (tid & 15) * 4;
    int tx = tid & 15, ty = tid >> 4;
    float acc[4][4] = {{0.f}};

    for (int k0 = 0; k0 < FDIM; k0 += BK) {
        float4 av = make_float4(0.f, 0.f, 0.f, 0.f);
        if (hrow) av = *reinterpret_cast<const float4*>(hrow + k0 + ak4);
        As[ak4 + 0][arow] = av.x;
        As[ak4 + 1][arow] = av.y;
        As[ak4 + 2][arow] = av.z;
        As[ak4 + 3][arow] = av.w;

        *reinterpret_cast<float4*>(&Bs[bk][bn4]) =
            *reinterpret_cast<const float4*>(wde + (size_t)(k0 + bk) * DIM + n0 + bn4);
        __syncthreads();

#pragma unroll
        for (int k = 0; k < BK; k++) {
            float a[4], b[4];
            *reinterpret_cast<float4*>(a) = *reinterpret_cast<const float4*>(&As[k][ty * 4]);
            *reinterpret_cast<float4*>(b) = *reinterpret_cast<const float4*>(&Bs[k][tx * 4]);
#pragma unroll
            for (int i = 0; i < 4; i++)
#pragma unroll
                for (int j = 0; j < 4; j++) acc[i][j] += a[i] * b[j];
        }
        __syncthreads();
    }

#pragma unroll
    for (int i = 0; i < 4; i++) {
        int m = ty * 4 + i;
        int pr = s_pr[m];
        if (pr < 0) continue;
        int token = pr >> 1;
        float w = s_w[m];
        float* op = out + (size_t)token * DIM + n0 + tx * 4;
#pragma unroll
        for (int j = 0; j < 4; j++) atomicAdd(op + j, w * acc[i][j]);
    }
}

// ---------------- launch ----------------
extern "C" void kernel_launch(void* const* d_in, const int* in_sizes, int n_in,
                              void* d_out, int out_size) {
    const float* x   = (const float*)d_in[0];
    const float* rw  = (const float*)d_in[1];
    const float* rb  = (const float*)d_in[2];
    const float* wgu = (const float*)d_in[3];
    const float* wd  = (const float*)d_in[4];
    float* out = (float*)d_out;

    cudaMemsetAsync(out, 0, (size_t)out_size * sizeof(float));
    zero_counts_kernel<<<1, 32>>>();
    router_kernel<<<NTOK / 8, 256>>>(x, rw, rb);
    gateup_kernel<<<dim3(FDIM / BN, NTOK / BM, NEXP), 256>>>(x, wgu);
    down_kernel<<<dim3(DIM / BN, NTOK / BM, NEXP), 256>>>(wd, out);
}

// round 2
// speedup vs baseline: 3.3029x; 3.3029x over previous
#include <cuda_runtime.h>
#include <math.h>
#include <stdint.h>

// Problem shape (fixed)
#define NTOK 8192      // B*T
#define DIM  512       // D
#define FDIM 1024      // F
#define NEXP 8         // E

// ---------------- scratch ----------------
__device__ int   g_expert_count[NEXP];
__device__ int   g_expert_pair[NEXP * NTOK];         // pair id = token*2 + slot
__device__ float g_pair_w[NTOK * 2];
__device__ float g_hbuf[(size_t)NTOK * 2 * FDIM];    // SwiGLU activations (tf32-rounded fp32)

// ---------------- PTX helpers ----------------
__device__ __forceinline__ uint32_t smem_u32(const void* p) {
    return (uint32_t)__cvta_generic_to_shared(p);
}
__device__ __forceinline__ void cpa16(uint32_t dst, const void* src, int sz) {
    asm volatile("cp.async.cg.shared.global [%0], [%1], 16, %2;\n"
                 :: "r"(dst), "l"(src), "r"(sz));
}
__device__ __forceinline__ void cp_commit() { asm volatile("cp.async.commit_group;\n"); }
__device__ __forceinline__ void cp_wait1()  { asm volatile("cp.async.wait_group 1;\n"); }
__device__ __forceinline__ uint32_t f2tf(float f) {
    uint32_t u; asm("cvt.rna.tf32.f32 %0, %1;" : "=r"(u) : "f"(f)); return u;
}
// D += A*B, m16n8k8 tf32, fp32 accumulate
__device__ __forceinline__ void mma8(float* d, const uint32_t* a, const uint32_t* b) {
    asm volatile("mma.sync.aligned.m16n8k8.row.col.f32.tf32.tf32.f32 "
                 "{%0,%1,%2,%3}, {%4,%5,%6,%7}, {%8,%9}, {%0,%1,%2,%3};\n"
                 : "+f"(d[0]), "+f"(d[1]), "+f"(d[2]), "+f"(d[3])
                 : "r"(a[0]), "r"(a[1]), "r"(a[2]), "r"(a[3]),
                   "r"(b[0]), "r"(b[1]));
}

// ---------------- kernel 0: zero counts ----------------
__global__ void zero_counts_kernel() {
    if (threadIdx.x < NEXP) g_expert_count[threadIdx.x] = 0;
}

// ---------------- kernel 1: router + dispatch ----------------
__global__ void router_kernel(const float* __restrict__ x,
                              const float* __restrict__ rw,
                              const float* __restrict__ rb) {
    __shared__ float sw[NEXP * DIM];
    int tid = threadIdx.x;
    for (int i = tid; i < NEXP * DIM; i += 256) sw[i] = rw[i];
    __syncthreads();

    int warp = tid >> 5, lane = tid & 31;
    int token = blockIdx.x * 8 + warp;
    if (token >= NTOK) return;

    const float* xr = x + (size_t)token * DIM;
    float acc[NEXP];
#pragma unroll
    for (int e = 0; e < NEXP; e++) acc[e] = 0.f;
    for (int i = lane; i < DIM; i += 32) {
        float xv = xr[i];
#pragma unroll
        for (int e = 0; e < NEXP; e++) acc[e] += xv * sw[e * DIM + i];
    }
#pragma unroll
    for (int e = 0; e < NEXP; e++) {
#pragma unroll
        for (int o = 16; o > 0; o >>= 1)
            acc[e] += __shfl_xor_sync(0xffffffffu, acc[e], o);
    }
    if (lane == 0) {
        float l[NEXP];
#pragma unroll
        for (int e = 0; e < NEXP; e++) l[e] = acc[e] + rb[e];
        int e1 = 0; float b1 = l[0];
#pragma unroll
        for (int e = 1; e < NEXP; e++) if (l[e] > b1) { b1 = l[e]; e1 = e; }
        int e2 = -1; float b2 = -INFINITY;
#pragma unroll
        for (int e = 0; e < NEXP; e++)
            if (e != e1 && l[e] > b2) { b2 = l[e]; e2 = e; }
        float t  = expf(b2 - b1);
        float w1 = 1.f / (1.f + t);
        float w2 = t   / (1.f + t);
        int pos1 = atomicAdd(&g_expert_count[e1], 1);
        g_expert_pair[e1 * NTOK + pos1] = token * 2;
        g_pair_w[token * 2] = w1;
        int pos2 = atomicAdd(&g_expert_count[e2], 1);
        g_expert_pair[e2 * NTOK + pos2] = token * 2 + 1;
        g_pair_w[token * 2 + 1] = w2;
    }
}

// ---------------- tensor-GEMM config ----------------
#define BM 128
#define BN 64
#define BK 32
#define BKP 36            // A smem row stride (words): banks (4r+c)%32 bijective
#define BNP 72            // B smem row stride (words): banks (8c+r)%32 bijective
#define ASZ (BM * BKP)    // 4608 words
#define BSZ (BK * BNP)    // 2304 words

// ---------------- kernel 2: gate_up GEMM (tf32 mma) + SwiGLU ----------------
// grid = (FDIM/BN, NTOK/BM, NEXP), 256 thr = 8 warps (4m x 2n), warp tile 32x32
__global__ void __launch_bounds__(256)
gateup_kernel(const float* __restrict__ x, const float* __restrict__ wgu) {
    int e = blockIdx.z;
    int count = g_expert_count[e];
    int m0 = blockIdx.y * BM;
    if (m0 >= count) return;
    int n0 = blockIdx.x * BN;
    int tid = threadIdx.x;

    extern __shared__ float dynsmem[];
    __shared__ int s_pr[BM];
    if (tid < BM) {
        int m = m0 + tid;
        s_pr[tid] = (m < count) ? g_expert_pair[e * NTOK + m] : -1;
    }
    __syncthreads();

    const float* wge = wgu + (size_t)e * DIM * (2 * FDIM);
    float* stage0 = dynsmem;
    float* stage1 = dynsmem + (ASZ + 2 * BSZ);

    // A-loader mapping: 4 chunks of 16B per thread
    int am[4], ac[4], asz[4];
    const float* asrc[4];
#pragma unroll
    for (int j = 0; j < 4; j++) {
        int idx = tid + 256 * j;
        am[j] = idx >> 3; ac[j] = (idx & 7) * 4;
        int pr = s_pr[am[j]];
        asz[j]  = (pr >= 0) ? 16 : 0;
        asrc[j] = (pr >= 0) ? (x + (size_t)(pr >> 1) * DIM + ac[j]) : x;
    }
    // B-loader mapping: 2 chunks per thread per matrix
    int bkx[2], bcx[2];
#pragma unroll
    for (int j = 0; j < 2; j++) {
        int idx = tid + 256 * j;
        bkx[j] = idx >> 4; bcx[j] = (idx & 15) * 4;
    }

    auto load_tile = [&](int kt, float* st) {
        float* As = st; float* Bg = st + ASZ; float* Bu = Bg + BSZ;
        int k0 = kt * BK;
#pragma unroll
        for (int j = 0; j < 4; j++)
            cpa16(smem_u32(As + am[j] * BKP + ac[j]), asrc[j] + k0, asz[j]);
#pragma unroll
        for (int j = 0; j < 2; j++) {
            const float* sg = wge + (size_t)(k0 + bkx[j]) * (2 * FDIM) + n0 + bcx[j];
            cpa16(smem_u32(Bg + bkx[j] * BNP + bcx[j]), sg, 16);
            cpa16(smem_u32(Bu + bkx[j] * BNP + bcx[j]), sg + FDIM, 16);
        }
    };

    int lane = tid & 31, warp = tid >> 5;
    int wm = (warp & 3) * 32, wn = (warp >> 2) * 32;
    int r = lane >> 2, c = lane & 3;

    float accg[2][4][4] = {{{0.f}}};
    float accu[2][4][4] = {{{0.f}}};

    load_tile(0, stage0);
    cp_commit();
    const int KT = DIM / BK;   // 16
    for (int kt = 0; kt < KT; kt++) {
        if (kt + 1 < KT) load_tile(kt + 1, ((kt + 1) & 1) ? stage1 : stage0);
        cp_commit();
        cp_wait1();
        __syncthreads();
        float* As = (kt & 1) ? stage1 : stage0;
        float* Bg = As + ASZ; float* Bu = Bg + BSZ;
#pragma unroll
        for (int k8 = 0; k8 < BK / 8; k8++) {
            uint32_t a[2][4];
#pragma unroll
            for (int i = 0; i < 2; i++) {
                const float* ap = As + (wm + i * 16 + r) * BKP + k8 * 8 + c;
                a[i][0] = f2tf(ap[0]);
                a[i][1] = f2tf(ap[8 * BKP]);
                a[i][2] = f2tf(ap[4]);
                a[i][3] = f2tf(ap[8 * BKP + 4]);
            }
            uint32_t bg[4][2], bu[4][2];
#pragma unroll
            for (int j = 0; j < 4; j++) {
                const float* bp = Bg + (k8 * 8 + c) * BNP + wn + j * 8 + r;
                bg[j][0] = f2tf(bp[0]); bg[j][1] = f2tf(bp[4 * BNP]);
                const float* bq = Bu + (k8 * 8 + c) * BNP + wn + j * 8 + r;
                bu[j][0] = f2tf(bq[0]); bu[j][1] = f2tf(bq[4 * BNP]);
            }
#pragma unroll
            for (int i = 0; i < 2; i++)
#pragma unroll
                for (int j = 0; j < 4; j++) {
                    mma8(accg[i][j], a[i], bg[j]);
                    mma8(accu[i][j], a[i], bu[j]);
                }
        }
        __syncthreads();
    }

    // epilogue: silu(g)*u -> hbuf (tf32-rounded so down needs no cvt on A)
#pragma unroll
    for (int i = 0; i < 2; i++) {
#pragma unroll
        for (int rr = 0; rr < 2; rr++) {
            int mrow = wm + i * 16 + r + rr * 8;
            int pr = s_pr[mrow];
            if (pr < 0) continue;
            float* hp = g_hbuf + (size_t)pr * FDIM + n0 + wn;
#pragma unroll
            for (int j = 0; j < 4; j++) {
                float g0 = accg[i][j][rr * 2 + 0], g1 = accg[i][j][rr * 2 + 1];
                float u0 = accu[i][j][rr * 2 + 0], u1 = accu[i][j][rr * 2 + 1];
                float h0 = g0 / (1.f + expf(-g0)) * u0;
                float h1 = g1 / (1.f + expf(-g1)) * u1;
                float2 hv = make_float2(__uint_as_float(f2tf(h0)),
                                        __uint_as_float(f2tf(h1)));
                *reinterpret_cast<float2*>(hp + j * 8 + 2 * c) = hv;
            }
        }
    }
}

// ---------------- kernel 3: down GEMM (tf32 mma) + weighted combine ----------------
// grid = (DIM/BN, NTOK/BM, NEXP)
__global__ void __launch_bounds__(256)
down_kernel(const float* __restrict__ wd, float* __restrict__ out) {
    int e = blockIdx.z;
    int count = g_expert_count[e];
    int m0 = blockIdx.y * BM;
    if (m0 >= count) return;
    int n0 = blockIdx.x * BN;
    int tid = threadIdx.x;

    extern __shared__ float dynsmem[];
    __shared__ int   s_pr[BM];
    __shared__ float s_w[BM];
    if (tid < BM) {
        int m = m0 + tid;
        int pr = (m < count) ? g_expert_pair[e * NTOK + m] : -1;
        s_pr[tid] = pr;
        s_w[tid]  = (pr >= 0) ? g_pair_w[pr] : 0.f;
    }
    __syncthreads();

    const float* wde = wd + (size_t)e * FDIM * DIM;
    float* stage0 = dynsmem;
    float* stage1 = dynsmem + (ASZ + BSZ);

    int am[4], ac[4], asz[4];
    const float* asrc[4];
#pragma unroll
    for (int j = 0; j < 4; j++) {
        int idx = tid + 256 * j;
        am[j] = idx >> 3; ac[j] = (idx & 7) * 4;
        int pr = s_pr[am[j]];
        asz[j]  = (pr >= 0) ? 16 : 0;
        asrc[j] = (pr >= 0) ? (g_hbuf + (size_t)pr * FDIM + ac[j]) : g_hbuf;
    }
    int bkx[2], bcx[2];
#pragma unroll
    for (int j = 0; j < 2; j++) {
        int idx = tid + 256 * j;
        bkx[j] = idx >> 4; bcx[j] = (idx & 15) * 4;
    }

    auto load_tile = [&](int kt, float* st) {
        float* As = st; float* Bs = st + ASZ;
        int k0 = kt * BK;
#pragma unroll
        for (int j = 0; j < 4; j++)
            cpa16(smem_u32(As + am[j] * BKP + ac[j]), asrc[j] + k0, asz[j]);
#pragma unroll
        for (int j = 0; j < 2; j++)
            cpa16(smem_u32(Bs + bkx[j] * BNP + bcx[j]),
                  wde + (size_t)(k0 + bkx[j]) * DIM + n0 + bcx[j], 16);
    };

    int lane = tid & 31, warp = tid >> 5;
    int wm = (warp & 3) * 32, wn = (warp >> 2) * 32;
    int r = lane >> 2, c = lane & 3;

    float acc[2][4][4] = {{{0.f}}};

    load_tile(0, stage0);
    cp_commit();
    const int KT = FDIM / BK;  // 32
    for (int kt = 0; kt < KT; kt++) {
        if (kt + 1 < KT) load_tile(kt + 1, ((kt + 1) & 1) ? stage1 : stage0);
        cp_commit();
        cp_wait1();
        __syncthreads();
        const float* As = (kt & 1) ? stage1 : stage0;
        const float* Bs = As + ASZ;
        const uint32_t* Au = reinterpret_cast<const uint32_t*>(As);
#pragma unroll
        for (int k8 = 0; k8 < BK / 8; k8++) {
            uint32_t a[2][4];
#pragma unroll
            for (int i = 0; i < 2; i++) {
                // hbuf is already tf32-rounded: raw bits are valid tf32
                const uint32_t* ap = Au + (wm + i * 16 + r) * BKP + k8 * 8 + c;
                a[i][0] = ap[0];
                a[i][1] = ap[8 * BKP];
                a[i][2] = ap[4];
                a[i][3] = ap[8 * BKP + 4];
            }
            uint32_t b[4][2];
#pragma unroll
            for (int j = 0; j < 4; j++) {
                const float* bp = Bs + (k8 * 8 + c) * BNP + wn + j * 8 + r;
                b[j][0] = f2tf(bp[0]); b[j][1] = f2tf(bp[4 * BNP]);
            }
#pragma unroll
            for (int i = 0; i < 2; i++)
#pragma unroll
                for (int j = 0; j < 4; j++) mma8(acc[i][j], a[i], b[j]);
        }
        __syncthreads();
    }

    // epilogue: out += w * acc (exactly 2 commutative atomics per element)
#pragma unroll
    for (int i = 0; i < 2; i++) {
#pragma unroll
        for (int rr = 0; rr < 2; rr++) {
            int mrow = wm + i * 16 + r + rr * 8;
            int pr = s_pr[mrow];
            if (pr < 0) continue;
            int token = pr >> 1;
            float w = s_w[mrow];
            float* op = out + (size_t)token * DIM + n0 + wn;
#pragma unroll
            for (int j = 0; j < 4; j++) {
                atomicAdd(op + j * 8 + 2 * c,     w * acc[i][j][rr * 2 + 0]);
                atomicAdd(op + j * 8 + 2 * c + 1, w * acc[i][j][rr * 2 + 1]);
            }
        }
    }
}

// ---------------- launch ----------------
extern "C" void kernel_launch(void* const* d_in, const int* in_sizes, int n_in,
                              void* d_out, int out_size) {
    const float* x   = (const float*)d_in[0];
    const float* rw  = (const float*)d_in[1];
    const float* rb  = (const float*)d_in[2];
    const float* wgu = (const float*)d_in[3];
    const float* wd  = (const float*)d_in[4];
    float* out = (float*)d_out;

    const int gu_smem = 2 * (ASZ + 2 * BSZ) * 4;   // 73728 B
    const int dn_smem = 2 * (ASZ + BSZ) * 4;       // 55296 B
    cudaFuncSetAttribute(gateup_kernel, cudaFuncAttributeMaxDynamicSharedMemorySize, gu_smem);
    cudaFuncSetAttribute(down_kernel,   cudaFuncAttributeMaxDynamicSharedMemorySize, dn_smem);

    cudaMemsetAsync(out, 0, (size_t)out_size * sizeof(float));
    zero_counts_kernel<<<1, 32>>>();
    router_kernel<<<NTOK / 8, 256>>>(x, rw, rb);
    gateup_kernel<<<dim3(FDIM / BN, NTOK / BM, NEXP), 256, gu_smem>>>(x, wgu);
    down_kernel<<<dim3(DIM / BN, NTOK / BM, NEXP), 256, dn_smem>>>(wd, out);
}